// round 6
// baseline (speedup 1.0000x reference)
#include <cuda_runtime.h>
#include <cuda_fp16.h>
#include <math.h>
#include <stdint.h>

// Problem constants: B=4, K=64, L=128, D=768
#define NBK   256
#define LL    128
#define DD    768
#define NROWS 65536
#define NOUT  32768
#define EPSV  1e-8f

#define ASTRH 40    // fp16 MLP smem row stride (80 B), ldmatrix conflict-free
#define SA2   68    // scores As stride (64 rows + pad)
#define SB2   132   // scores Bs stride (128 rows + pad)

// Scratch
__device__ float  g_norm[NROWS];
__device__ int    g_arg[NOUT];
__device__ float  g_y[NROWS];
__device__ __half g_w1h[DD * DD];   // w1^T fp16 [e][d]

__device__ __forceinline__ void ldsm_x4(uint32_t* r, uint32_t addr) {
    asm volatile("ldmatrix.sync.aligned.m8n8.x4.shared.b16 {%0,%1,%2,%3}, [%4];"
        : "=r"(r[0]), "=r"(r[1]), "=r"(r[2]), "=r"(r[3]) : "r"(addr));
}
__device__ __forceinline__ void mma_fp16(float* d, const uint32_t* a, const uint32_t* b) {
    asm volatile(
        "mma.sync.aligned.m16n8k16.row.col.f32.f16.f16.f32 "
        "{%0,%1,%2,%3}, {%4,%5,%6,%7}, {%8,%9}, {%0,%1,%2,%3};"
        : "+f"(d[0]), "+f"(d[1]), "+f"(d[2]), "+f"(d[3])
        : "r"(a[0]), "r"(a[1]), "r"(a[2]), "r"(a[3]), "r"(b[0]), "r"(b[1]));
}
__device__ __forceinline__ uint32_t smem_u32(const void* p) {
    uint32_t a;
    asm("{ .reg .u64 t; cvta.to.shared.u64 t, %1; cvt.u32.u64 %0, t; }" : "=r"(a) : "l"(p));
    return a;
}
__device__ __forceinline__ uint32_t pack2(float x, float y) {
    __half2 h = __floats2half2_rn(x, y);
    return *reinterpret_cast<uint32_t*>(&h);
}

// ---------------------------------------------------------------------------
// Kernel A: L2 norms (one warp per row)
// ---------------------------------------------------------------------------
__global__ void norms_kernel(const float* __restrict__ x) {
    int row  = blockIdx.x * 8 + (threadIdx.x >> 5);
    int lane = threadIdx.x & 31;
    const float4* p = reinterpret_cast<const float4*>(x) + (size_t)row * (DD / 4);
    float s = 0.f;
    #pragma unroll
    for (int i = 0; i < 6; i++) {
        float4 v = p[lane + i * 32];
        s += v.x * v.x + v.y * v.y + v.z * v.z + v.w * v.w;
    }
    #pragma unroll
    for (int o = 16; o; o >>= 1) s += __shfl_xor_sync(0xffffffffu, s, o);
    if (lane == 0) g_norm[row] = sqrtf(s);
}

// ---------------------------------------------------------------------------
// Kernel B: w1 -> fp16, transposed to [e][d]
// ---------------------------------------------------------------------------
__global__ void prep_w1_kernel(const float* __restrict__ w1) {
    int e = blockIdx.x;
    for (int d = threadIdx.x; d < DD; d += 256)
        g_w1h[e * DD + d] = __float2half_rn(__ldg(w1 + (size_t)d * DD + e));
}

// ---------------------------------------------------------------------------
// MLP body: fp16 m16n8k16 + ldmatrix, double-buffered (validated in R5)
// ---------------------------------------------------------------------------
#define ABUF (128 * ASTRH)
#define MLP_OFF_AS   0
#define MLP_OFF_BS   20480
#define MLP_OFF_SINV 40960
#define MLP_OFF_SRED 41472
#define MLP_SMEM     42496

__device__ __forceinline__ void mlp_body(char* smem, int rt,
                                         const float* __restrict__ x,
                                         const float* __restrict__ b1,
                                         const float* __restrict__ w2,
                                         const float* __restrict__ b2) {
    __half* As   = reinterpret_cast<__half*>(smem + MLP_OFF_AS);
    __half* Bs   = reinterpret_cast<__half*>(smem + MLP_OFF_BS);
    float*  sinv = reinterpret_cast<float*>(smem + MLP_OFF_SINV);
    float*  sred = reinterpret_cast<float*>(smem + MLP_OFF_SRED);
    uint32_t as_u32 = smem_u32(As);
    uint32_t bs_u32 = smem_u32(Bs);

    const float* X = x + (size_t)rt * LL * DD;

    int t    = threadIdx.x;
    int lane = t & 31;
    int wid  = t >> 5;
    int wm   = wid & 3;
    int wn   = wid >> 2;
    int lq   = lane >> 2;
    int lr   = lane & 3;

    if (t < 128) sinv[t] = 1.0f / g_norm[rt * LL + t];
    __syncthreads();

    int arow[4], ak4[4];
    #pragma unroll
    for (int it = 0; it < 4; it++) {
        int idx = t + it * 256;
        arow[it] = idx >> 3;  ak4[it] = idx & 7;
    }
    int bn[2], bj[2];
    #pragma unroll
    for (int it = 0; it < 2; it++) {
        int idx = t + it * 256;
        bn[it] = idx >> 2;  bj[it] = idx & 3;
    }

    uint32_t a_frag_base = as_u32 +
        (uint32_t)(((wm * 32 + (lane & 15)) * ASTRH + (lane >> 4) * 8) * 2);
    uint32_t b_row_off = ((lane >> 4) * 8 + (lane & 7));
    uint32_t b_k_off   = ((lane >> 3) & 1) * 8;
    uint32_t b_frag_base = bs_u32 +
        (uint32_t)(((wn * 64 + b_row_off) * ASTRH + b_k_off) * 2);

    float yacc[4] = {0.f, 0.f, 0.f, 0.f};

    for (int ec = 0; ec < 6; ec++) {
        float acc[2][8][4];
        #pragma unroll
        for (int mi = 0; mi < 2; mi++)
            #pragma unroll
            for (int ni = 0; ni < 8; ni++)
                #pragma unroll
                for (int c = 0; c < 4; c++) acc[mi][ni][c] = 0.f;

        float4 av[4];
        uint4  bv[2];
        #pragma unroll
        for (int it = 0; it < 4; it++)
            av[it] = *reinterpret_cast<const float4*>(X + (size_t)arow[it] * DD + ak4[it] * 4);
        #pragma unroll
        for (int it = 0; it < 2; it++)
            bv[it] = *reinterpret_cast<const uint4*>(&g_w1h[(size_t)(ec * 128 + bn[it]) * DD + bj[it] * 8]);
        #pragma unroll
        for (int it = 0; it < 4; it++) {
            float sc = sinv[arow[it]];
            uint2 u;
            u.x = pack2(av[it].x * sc, av[it].y * sc);
            u.y = pack2(av[it].z * sc, av[it].w * sc);
            *reinterpret_cast<uint2*>(&As[arow[it] * ASTRH + ak4[it] * 4]) = u;
        }
        #pragma unroll
        for (int it = 0; it < 2; it++)
            *reinterpret_cast<uint4*>(&Bs[bn[it] * ASTRH + bj[it] * 8]) = bv[it];
        __syncthreads();

        for (int c = 0; c < 24; c++) {
            int buf = c & 1;
            if (c < 23) {
                int d0 = (c + 1) * 32;
                #pragma unroll
                for (int it = 0; it < 4; it++)
                    av[it] = *reinterpret_cast<const float4*>(X + (size_t)arow[it] * DD + d0 + ak4[it] * 4);
                #pragma unroll
                for (int it = 0; it < 2; it++)
                    bv[it] = *reinterpret_cast<const uint4*>(&g_w1h[(size_t)(ec * 128 + bn[it]) * DD + d0 + bj[it] * 8]);
            }
            uint32_t abase = a_frag_base + buf * (ABUF * 2);
            uint32_t bbase = b_frag_base + buf * (ABUF * 2);
            #pragma unroll
            for (int kk = 0; kk < 2; kk++) {
                uint32_t a[2][4];
                #pragma unroll
                for (int mi = 0; mi < 2; mi++)
                    ldsm_x4(a[mi], abase + mi * (16 * ASTRH * 2) + kk * 32);
                uint32_t b[4][4];
                #pragma unroll
                for (int nb = 0; nb < 4; nb++)
                    ldsm_x4(b[nb], bbase + nb * (16 * ASTRH * 2) + kk * 32);
                #pragma unroll
                for (int mi = 0; mi < 2; mi++)
                    #pragma unroll
                    for (int nb = 0; nb < 4; nb++) {
                        mma_fp16(acc[mi][nb * 2 + 0], a[mi], &b[nb][0]);
                        mma_fp16(acc[mi][nb * 2 + 1], a[mi], &b[nb][2]);
                    }
            }
            if (c < 23) {
                __half* Ad = As + (buf ^ 1) * ABUF;
                __half* Bd = Bs + (buf ^ 1) * ABUF;
                #pragma unroll
                for (int it = 0; it < 4; it++) {
                    float sc = sinv[arow[it]];
                    uint2 u;
                    u.x = pack2(av[it].x * sc, av[it].y * sc);
                    u.y = pack2(av[it].z * sc, av[it].w * sc);
                    *reinterpret_cast<uint2*>(&Ad[arow[it] * ASTRH + ak4[it] * 4]) = u;
                }
                #pragma unroll
                for (int it = 0; it < 2; it++)
                    *reinterpret_cast<uint4*>(&Bd[bn[it] * ASTRH + bj[it] * 8]) = bv[it];
            }
            __syncthreads();
        }

        #pragma unroll
        for (int ni = 0; ni < 8; ni++) {
            int e0 = ec * 128 + wn * 64 + ni * 8 + lr * 2;
            float b1a = __ldg(b1 + e0),     b1b = __ldg(b1 + e0 + 1);
            float w2a = __ldg(w2 + e0),     w2b = __ldg(w2 + e0 + 1);
            #pragma unroll
            for (int mi = 0; mi < 2; mi++) {
                float h;
                h = acc[mi][ni][0] + b1a; if (h > 0.f) yacc[mi * 2 + 0] += h * w2a;
                h = acc[mi][ni][1] + b1b; if (h > 0.f) yacc[mi * 2 + 0] += h * w2b;
                h = acc[mi][ni][2] + b1a; if (h > 0.f) yacc[mi * 2 + 1] += h * w2a;
                h = acc[mi][ni][3] + b1b; if (h > 0.f) yacc[mi * 2 + 1] += h * w2b;
            }
        }
    }

    #pragma unroll
    for (int j = 0; j < 4; j++) {
        yacc[j] += __shfl_xor_sync(0xffffffffu, yacc[j], 1);
        yacc[j] += __shfl_xor_sync(0xffffffffu, yacc[j], 2);
    }
    if (lr == 0) {
        #pragma unroll
        for (int j = 0; j < 4; j++) {
            int row = wm * 32 + (j >> 1) * 16 + (j & 1) * 8 + lq;
            sred[row * 2 + wn] = yacc[j];
        }
    }
    __syncthreads();
    if (t < 128)
        g_y[rt * LL + t] = sred[t * 2] + sred[t * 2 + 1] + __ldg(b2);
}

// ---------------------------------------------------------------------------
// Scores body: half-tile (64 l-rows x 128 m), exact fp32 FFMA + argmax.
// ---------------------------------------------------------------------------
__device__ __forceinline__ void scores_body(char* smem, int hb,
                                            const float* __restrict__ x) {
    float* As = reinterpret_cast<float*>(smem);             // [32][SA2]
    float* Bs = reinterpret_cast<float*>(smem) + 32 * SA2;  // [32][SB2]

    int bk = hb >> 1;
    int lo = (hb & 1) * 64;
    const float* ctx = x + (size_t)(bk * 2) * LL * DD + (size_t)lo * DD;
    const float* ent = x + (size_t)(bk * 2 + 1) * LL * DD;

    int t  = threadIdx.x;
    int tx = t & 15;
    int ty = t >> 4;

    float C[4][8];
    #pragma unroll
    for (int a = 0; a < 4; a++)
        #pragma unroll
        for (int b = 0; b < 8; b++) C[a][b] = 0.f;

    for (int d0 = 0; d0 < DD; d0 += 32) {
        // ctx: 64 rows x 8 float4 = 512 slots (2/thread)
        #pragma unroll
        for (int it = 0; it < 2; it++) {
            int idx = t + it * 256;
            int i  = idx >> 3;
            int k4 = idx & 7;
            float4 v = *reinterpret_cast<const float4*>(ctx + (size_t)i * DD + d0 + k4 * 4);
            As[(k4 * 4 + 0) * SA2 + i] = v.x;
            As[(k4 * 4 + 1) * SA2 + i] = v.y;
            As[(k4 * 4 + 2) * SA2 + i] = v.z;
            As[(k4 * 4 + 3) * SA2 + i] = v.w;
        }
        // ent: 128 rows x 8 float4 = 1024 slots (4/thread)
        #pragma unroll
        for (int it = 0; it < 4; it++) {
            int idx = t + it * 256;
            int i  = idx >> 3;
            int k4 = idx & 7;
            float4 w = *reinterpret_cast<const float4*>(ent + (size_t)i * DD + d0 + k4 * 4);
            Bs[(k4 * 4 + 0) * SB2 + i] = w.x;
            Bs[(k4 * 4 + 1) * SB2 + i] = w.y;
            Bs[(k4 * 4 + 2) * SB2 + i] = w.z;
            Bs[(k4 * 4 + 3) * SB2 + i] = w.w;
        }
        __syncthreads();
        #pragma unroll 8
        for (int kk = 0; kk < 32; kk++) {
            float a[4], b[8];
            #pragma unroll
            for (int i = 0; i < 4; i++) a[i] = As[kk * SA2 + ty * 4 + i];
            #pragma unroll
            for (int j = 0; j < 8; j++) b[j] = Bs[kk * SB2 + tx * 8 + j];
            #pragma unroll
            for (int i = 0; i < 4; i++)
                #pragma unroll
                for (int j = 0; j < 8; j++) C[i][j] += a[i] * b[j];
        }
        __syncthreads();
    }

    float nl[4], nm[8];
    #pragma unroll
    for (int a = 0; a < 4; a++) nl[a] = g_norm[(bk * 2) * LL + lo + ty * 4 + a];
    #pragma unroll
    for (int b = 0; b < 8; b++) nm[b] = g_norm[(bk * 2 + 1) * LL + tx * 8 + b];

    float bestv[4];
    int   besti[4];
    #pragma unroll
    for (int a = 0; a < 4; a++) { bestv[a] = -3.4e38f; besti[a] = 0; }
    #pragma unroll
    for (int b = 0; b < 8; b++) {
        #pragma unroll
        for (int a = 0; a < 4; a++) {
            float s = C[a][b] / (nl[a] * nm[b] + EPSV);
            if (s > bestv[a]) { bestv[a] = s; besti[a] = tx * 8 + b; }
        }
    }

    float* rv = reinterpret_cast<float*>(smem);             // 64*16
    int*   ri = reinterpret_cast<int*>(rv + 64 * 16);
    #pragma unroll
    for (int a = 0; a < 4; a++) {
        rv[(ty * 4 + a) * 16 + tx] = bestv[a];
        ri[(ty * 4 + a) * 16 + tx] = besti[a];
    }
    __syncthreads();
    if (t < 64) {
        float bv = -3.4e38f; int bi = 0;
        #pragma unroll
        for (int j = 0; j < 16; j++) {
            float v = rv[t * 16 + j];
            if (v > bv) { bv = v; bi = ri[t * 16 + j]; }
        }
        g_arg[bk * LL + lo + t] = bi;
    }
}

// ---------------------------------------------------------------------------
// Megakernel: even blocks = MLP tile, odd blocks = scores half-tile.
// Interleaved so tensor-pipe and FMA-pipe blocks co-schedule on each SM.
// ---------------------------------------------------------------------------
__global__ __launch_bounds__(256, 2) void mega_kernel(const float* __restrict__ x,
                                                      const float* __restrict__ b1,
                                                      const float* __restrict__ w2,
                                                      const float* __restrict__ b2) {
    extern __shared__ char smem[];
    int id = blockIdx.x >> 1;
    if ((blockIdx.x & 1) == 0) {
        mlp_body(smem, id, x, b1, w2, b2);
    } else {
        scores_body(smem, id, x);
    }
}

// ---------------------------------------------------------------------------
// Kernel C: out = y_ctx + y_ent[argmax]
// ---------------------------------------------------------------------------
__global__ void finalize_kernel(float* __restrict__ out) {
    int i  = blockIdx.x * 256 + threadIdx.x;
    int bk = i >> 7;
    float yc = g_y[(bk * 2) * LL + (i & 127)];
    float ye = g_y[(bk * 2 + 1) * LL + g_arg[i]];
    out[i] = yc + ye;
}

extern "C" void kernel_launch(void* const* d_in, const int* in_sizes, int n_in,
                              void* d_out, int out_size) {
    const float* context = (const float*)d_in[0];
    const float* w1      = (const float*)d_in[1];
    const float* b1      = (const float*)d_in[2];
    const float* w2      = (const float*)d_in[3];
    const float* b2      = (const float*)d_in[4];
    float* out = (float*)d_out;

    cudaFuncSetAttribute(mega_kernel,
                         cudaFuncAttributeMaxDynamicSharedMemorySize, MLP_SMEM);

    norms_kernel<<<NROWS / 8, 256>>>(context);
    prep_w1_kernel<<<DD, 256>>>(w1);
    mega_kernel<<<1024, 256, MLP_SMEM>>>(context, b1, w2, b2);
    finalize_kernel<<<NOUT / 256, 256>>>(out);
}

// round 7
// speedup vs baseline: 1.4344x; 1.4344x over previous
#include <cuda_runtime.h>
#include <cuda_fp16.h>
#include <math.h>
#include <stdint.h>

// Problem constants: B=4, K=64, L=128, D=768
#define NBK   256
#define LL    128
#define DD    768
#define NROWS 65536
#define NOUT  32768
#define EPSV  1e-8f

#define ASTRH 40    // fp16 smem row stride (80 B), ldmatrix conflict-free
#define SSTR  136   // fp16 score smem stride
#define MARGIN 3e-3f
#define MAXCAND 1024

// Scratch
__device__ float  g_norm[NROWS];
__device__ int    g_arg[NOUT];
__device__ float  g_y[NROWS];
__device__ __half g_w1h[DD * DD];   // w1^T fp16 [e][d]

__device__ __forceinline__ void ldsm_x4(uint32_t* r, uint32_t addr) {
    asm volatile("ldmatrix.sync.aligned.m8n8.x4.shared.b16 {%0,%1,%2,%3}, [%4];"
        : "=r"(r[0]), "=r"(r[1]), "=r"(r[2]), "=r"(r[3]) : "r"(addr));
}
__device__ __forceinline__ void mma_fp16(float* d, const uint32_t* a, const uint32_t* b) {
    asm volatile(
        "mma.sync.aligned.m16n8k16.row.col.f32.f16.f16.f32 "
        "{%0,%1,%2,%3}, {%4,%5,%6,%7}, {%8,%9}, {%0,%1,%2,%3};"
        : "+f"(d[0]), "+f"(d[1]), "+f"(d[2]), "+f"(d[3])
        : "r"(a[0]), "r"(a[1]), "r"(a[2]), "r"(a[3]), "r"(b[0]), "r"(b[1]));
}
__device__ __forceinline__ uint32_t smem_u32(const void* p) {
    uint32_t a;
    asm("{ .reg .u64 t; cvta.to.shared.u64 t, %1; cvt.u32.u64 %0, t; }" : "=r"(a) : "l"(p));
    return a;
}
__device__ __forceinline__ uint32_t pack2(float x, float y) {
    __half2 h = __floats2half2_rn(x, y);
    return *reinterpret_cast<uint32_t*>(&h);
}

// ---------------------------------------------------------------------------
// Kernel 0: w1 -> fp16, transposed to [e][d]
// ---------------------------------------------------------------------------
__global__ void prep_w1_kernel(const float* __restrict__ w1) {
    int e = blockIdx.x;
    for (int d = threadIdx.x; d < DD; d += 256)
        g_w1h[e * DD + d] = __float2half_rn(__ldg(w1 + (size_t)d * DD + e));
}

// ---------------------------------------------------------------------------
// Kernel 1: scores via fp16 tensor cores + exact fp32 recheck of near-ties.
// Also computes row norms (fused into tile loads) -> g_norm.
// ---------------------------------------------------------------------------
#define ABUF (128 * ASTRH)
#define SC_AS    0                  // 2 x 10240 B (ctx fp16 tiles)
#define SC_BS    20480              // 2 x 10240 B (ent fp16 tiles)
#define SC_SNA   40960              // f32[128]
#define SC_SNB   41472              // f32[128]
#define SC_SS    41984              // fp16 [128][SSTR] = 34816 B
#define SC_CNT   76800              // u32
#define SC_CAND  76816              // u32[MAXCAND]
#define SC_EXACT 80912              // f32[MAXCAND]
#define SC_SMEM  85008

__global__ __launch_bounds__(256, 2) void scores_tc_kernel(const float* __restrict__ x) {
    extern __shared__ char smem[];
    __half*   As   = reinterpret_cast<__half*>(smem + SC_AS);
    __half*   Bs   = reinterpret_cast<__half*>(smem + SC_BS);
    float*    snA  = reinterpret_cast<float*>(smem + SC_SNA);
    float*    snB  = reinterpret_cast<float*>(smem + SC_SNB);
    __half*   ss   = reinterpret_cast<__half*>(smem + SC_SS);
    unsigned* cnt  = reinterpret_cast<unsigned*>(smem + SC_CNT);
    unsigned* cand = reinterpret_cast<unsigned*>(smem + SC_CAND);
    float*    cex  = reinterpret_cast<float*>(smem + SC_EXACT);
    uint32_t as_u32 = smem_u32(As);
    uint32_t bs_u32 = smem_u32(Bs);

    int bk = blockIdx.x;
    const float* ctx = x + (size_t)(bk * 2) * LL * DD;
    const float* ent = ctx + (size_t)LL * DD;

    int t    = threadIdx.x;
    int lane = t & 31;
    int wid  = t >> 5;
    int wm   = wid & 3;
    int wn   = wid >> 2;
    int lq   = lane >> 2;
    int lr   = lane & 3;

    if (t == 0) *cnt = 0;

    int arow[4], ak4[4];
    #pragma unroll
    for (int it = 0; it < 4; it++) {
        int idx = t + it * 256;
        arow[it] = idx >> 3;  ak4[it] = idx & 7;
    }

    uint32_t a_frag_base = as_u32 +
        (uint32_t)(((wm * 32 + (lane & 15)) * ASTRH + (lane >> 4) * 8) * 2);
    uint32_t b_row_off = ((lane >> 4) * 8 + (lane & 7));
    uint32_t b_k_off   = ((lane >> 3) & 1) * 8;
    uint32_t b_frag_base = bs_u32 +
        (uint32_t)(((wn * 64 + b_row_off) * ASTRH + b_k_off) * 2);

    float acc[2][8][4];
    #pragma unroll
    for (int mi = 0; mi < 2; mi++)
        #pragma unroll
        for (int ni = 0; ni < 8; ni++)
            #pragma unroll
            for (int c = 0; c < 4; c++) acc[mi][ni][c] = 0.f;

    float nsA[4] = {0.f, 0.f, 0.f, 0.f};
    float nsB[4] = {0.f, 0.f, 0.f, 0.f};

    float4 av[4], bw[4];
    // prologue: chunk 0
    #pragma unroll
    for (int it = 0; it < 4; it++) {
        av[it] = *reinterpret_cast<const float4*>(ctx + (size_t)arow[it] * DD + ak4[it] * 4);
        bw[it] = *reinterpret_cast<const float4*>(ent + (size_t)arow[it] * DD + ak4[it] * 4);
        nsA[it] += av[it].x * av[it].x + av[it].y * av[it].y + av[it].z * av[it].z + av[it].w * av[it].w;
        nsB[it] += bw[it].x * bw[it].x + bw[it].y * bw[it].y + bw[it].z * bw[it].z + bw[it].w * bw[it].w;
    }
    #pragma unroll
    for (int it = 0; it < 4; it++) {
        uint2 ua, ub;
        ua.x = pack2(av[it].x, av[it].y); ua.y = pack2(av[it].z, av[it].w);
        ub.x = pack2(bw[it].x, bw[it].y); ub.y = pack2(bw[it].z, bw[it].w);
        *reinterpret_cast<uint2*>(&As[arow[it] * ASTRH + ak4[it] * 4]) = ua;
        *reinterpret_cast<uint2*>(&Bs[arow[it] * ASTRH + ak4[it] * 4]) = ub;
    }
    __syncthreads();

    for (int c = 0; c < 24; c++) {
        int buf = c & 1;
        if (c < 23) {
            int d0 = (c + 1) * 32;
            #pragma unroll
            for (int it = 0; it < 4; it++) {
                av[it] = *reinterpret_cast<const float4*>(ctx + (size_t)arow[it] * DD + d0 + ak4[it] * 4);
                bw[it] = *reinterpret_cast<const float4*>(ent + (size_t)arow[it] * DD + d0 + ak4[it] * 4);
                nsA[it] += av[it].x * av[it].x + av[it].y * av[it].y + av[it].z * av[it].z + av[it].w * av[it].w;
                nsB[it] += bw[it].x * bw[it].x + bw[it].y * bw[it].y + bw[it].z * bw[it].z + bw[it].w * bw[it].w;
            }
        }
        uint32_t abase = a_frag_base + buf * (ABUF * 2);
        uint32_t bbase = b_frag_base + buf * (ABUF * 2);
        #pragma unroll
        for (int kk = 0; kk < 2; kk++) {
            uint32_t a[2][4];
            #pragma unroll
            for (int mi = 0; mi < 2; mi++)
                ldsm_x4(a[mi], abase + mi * (16 * ASTRH * 2) + kk * 32);
            uint32_t b[4][4];
            #pragma unroll
            for (int nb = 0; nb < 4; nb++)
                ldsm_x4(b[nb], bbase + nb * (16 * ASTRH * 2) + kk * 32);
            #pragma unroll
            for (int mi = 0; mi < 2; mi++)
                #pragma unroll
                for (int nb = 0; nb < 4; nb++) {
                    mma_fp16(acc[mi][nb * 2 + 0], a[mi], &b[nb][0]);
                    mma_fp16(acc[mi][nb * 2 + 1], a[mi], &b[nb][2]);
                }
        }
        if (c < 23) {
            __half* Ad = As + (buf ^ 1) * ABUF;
            __half* Bd = Bs + (buf ^ 1) * ABUF;
            #pragma unroll
            for (int it = 0; it < 4; it++) {
                uint2 ua, ub;
                ua.x = pack2(av[it].x, av[it].y); ua.y = pack2(av[it].z, av[it].w);
                ub.x = pack2(bw[it].x, bw[it].y); ub.y = pack2(bw[it].z, bw[it].w);
                *reinterpret_cast<uint2*>(&Ad[arow[it] * ASTRH + ak4[it] * 4]) = ua;
                *reinterpret_cast<uint2*>(&Bd[arow[it] * ASTRH + ak4[it] * 4]) = ub;
            }
        }
        __syncthreads();
    }

    // finish norms: reduce over the 8 lanes sharing a row
    #pragma unroll
    for (int it = 0; it < 4; it++) {
        float sA = nsA[it], sB = nsB[it];
        #pragma unroll
        for (int o = 1; o < 8; o <<= 1) {
            sA += __shfl_xor_sync(0xffffffffu, sA, o);
            sB += __shfl_xor_sync(0xffffffffu, sB, o);
        }
        if ((t & 7) == 0) {
            int row = arow[it];
            float na = sqrtf(sA), nb = sqrtf(sB);
            snA[row] = na;
            snB[row] = nb;
            g_norm[(bk * 2) * LL + row]     = na;
            g_norm[(bk * 2 + 1) * LL + row] = nb;
        }
    }

    // store approx scores (fp16) to smem
    #pragma unroll
    for (int mi = 0; mi < 2; mi++)
        #pragma unroll
        for (int ni = 0; ni < 8; ni++) {
            int row0 = wm * 32 + mi * 16 + lq;
            int col  = wn * 64 + ni * 8 + lr * 2;
            __half2 h01 = __floats2half2_rn(acc[mi][ni][0], acc[mi][ni][1]);
            __half2 h23 = __floats2half2_rn(acc[mi][ni][2], acc[mi][ni][3]);
            *reinterpret_cast<__half2*>(&ss[row0 * SSTR + col]) = h01;
            *reinterpret_cast<__half2*>(&ss[(row0 + 8) * SSTR + col]) = h23;
        }
    __syncthreads();

    // per-row approx max, then collect near-tie candidates
    if (t < 128) {
        float nl = snA[t];
        float amax = -3.4e38f;
        #pragma unroll 8
        for (int j = 0; j < 128; j++) {
            float s = __half2float(ss[t * SSTR + j]);
            float cv = s / (nl * snB[j] + EPSV);
            if (cv > amax) amax = cv;
        }
        float thr = amax - MARGIN;
        for (int j = 0; j < 128; j++) {
            float s = __half2float(ss[t * SSTR + j]);
            float cv = s / (nl * snB[j] + EPSV);
            if (cv >= thr) {
                unsigned id = atomicAdd(cnt, 1u);
                if (id < MAXCAND) cand[id] = ((unsigned)t << 16) | (unsigned)j;
            }
        }
    }
    __syncthreads();

    unsigned n = *cnt;
    if (n > MAXCAND) n = MAXCAND;

    // exact fp32 dots: one warp per candidate
    for (unsigned ci = wid; ci < n; ci += 8) {
        unsigned m = cand[ci];
        int row = m >> 16, col = m & 0xffff;
        const float4* pa = reinterpret_cast<const float4*>(ctx + (size_t)row * DD);
        const float4* pb = reinterpret_cast<const float4*>(ent + (size_t)col * DD);
        float d = 0.f;
        #pragma unroll
        for (int i = 0; i < 6; i++) {
            float4 a = pa[lane + i * 32];
            float4 b = pb[lane + i * 32];
            d += a.x * b.x + a.y * b.y + a.z * b.z + a.w * b.w;
        }
        #pragma unroll
        for (int o = 16; o; o >>= 1) d += __shfl_xor_sync(0xffffffffu, d, o);
        if (lane == 0)
            cex[ci] = d / (snA[row] * snB[col] + EPSV);
    }
    __syncthreads();

    // final exact argmax per row (candidates for a row arrive in ascending j,
    // so strict > preserves first-index tie-break)
    if (t < 128) {
        float best = -3.4e38f; int bi = 0;
        for (unsigned ci = 0; ci < n; ci++) {
            unsigned m = cand[ci];
            if ((int)(m >> 16) == t) {
                float v = cex[ci];
                if (v > best) { best = v; bi = (int)(m & 0xffff); }
            }
        }
        g_arg[bk * LL + t] = bi;
    }
}

// ---------------------------------------------------------------------------
// Kernel 2: MLP via fp16 m16n8k16 mma.sync + ldmatrix (R5, validated)
// ---------------------------------------------------------------------------
#define MLP_OFF_AS   0
#define MLP_OFF_BS   20480
#define MLP_OFF_SINV 40960
#define MLP_OFF_SRED 41472
#define MLP_SMEM     42496

__global__ __launch_bounds__(256, 2) void mlp_tc_kernel(const float* __restrict__ x,
                                                        const float* __restrict__ b1,
                                                        const float* __restrict__ w2,
                                                        const float* __restrict__ b2) {
    extern __shared__ char smem[];
    __half* As   = reinterpret_cast<__half*>(smem + MLP_OFF_AS);
    __half* Bs   = reinterpret_cast<__half*>(smem + MLP_OFF_BS);
    float*  sinv = reinterpret_cast<float*>(smem + MLP_OFF_SINV);
    float*  sred = reinterpret_cast<float*>(smem + MLP_OFF_SRED);
    uint32_t as_u32 = smem_u32(As);
    uint32_t bs_u32 = smem_u32(Bs);

    int rt = blockIdx.x;
    const float* X = x + (size_t)rt * LL * DD;

    int t    = threadIdx.x;
    int lane = t & 31;
    int wid  = t >> 5;
    int wm   = wid & 3;
    int wn   = wid >> 2;
    int lq   = lane >> 2;
    int lr   = lane & 3;

    if (t < 128) sinv[t] = 1.0f / g_norm[rt * LL + t];
    __syncthreads();

    int arow[4], ak4[4];
    #pragma unroll
    for (int it = 0; it < 4; it++) {
        int idx = t + it * 256;
        arow[it] = idx >> 3;  ak4[it] = idx & 7;
    }
    int bn[2], bj[2];
    #pragma unroll
    for (int it = 0; it < 2; it++) {
        int idx = t + it * 256;
        bn[it] = idx >> 2;  bj[it] = idx & 3;
    }

    uint32_t a_frag_base = as_u32 +
        (uint32_t)(((wm * 32 + (lane & 15)) * ASTRH + (lane >> 4) * 8) * 2);
    uint32_t b_row_off = ((lane >> 4) * 8 + (lane & 7));
    uint32_t b_k_off   = ((lane >> 3) & 1) * 8;
    uint32_t b_frag_base = bs_u32 +
        (uint32_t)(((wn * 64 + b_row_off) * ASTRH + b_k_off) * 2);

    float yacc[4] = {0.f, 0.f, 0.f, 0.f};

    for (int ec = 0; ec < 6; ec++) {
        float acc[2][8][4];
        #pragma unroll
        for (int mi = 0; mi < 2; mi++)
            #pragma unroll
            for (int ni = 0; ni < 8; ni++)
                #pragma unroll
                for (int c = 0; c < 4; c++) acc[mi][ni][c] = 0.f;

        float4 av[4];
        uint4  bv[2];
        #pragma unroll
        for (int it = 0; it < 4; it++)
            av[it] = *reinterpret_cast<const float4*>(X + (size_t)arow[it] * DD + ak4[it] * 4);
        #pragma unroll
        for (int it = 0; it < 2; it++)
            bv[it] = *reinterpret_cast<const uint4*>(&g_w1h[(size_t)(ec * 128 + bn[it]) * DD + bj[it] * 8]);
        #pragma unroll
        for (int it = 0; it < 4; it++) {
            float sc = sinv[arow[it]];
            uint2 u;
            u.x = pack2(av[it].x * sc, av[it].y * sc);
            u.y = pack2(av[it].z * sc, av[it].w * sc);
            *reinterpret_cast<uint2*>(&As[arow[it] * ASTRH + ak4[it] * 4]) = u;
        }
        #pragma unroll
        for (int it = 0; it < 2; it++)
            *reinterpret_cast<uint4*>(&Bs[bn[it] * ASTRH + bj[it] * 8]) = bv[it];
        __syncthreads();

        for (int c = 0; c < 24; c++) {
            int buf = c & 1;
            if (c < 23) {
                int d0 = (c + 1) * 32;
                #pragma unroll
                for (int it = 0; it < 4; it++)
                    av[it] = *reinterpret_cast<const float4*>(X + (size_t)arow[it] * DD + d0 + ak4[it] * 4);
                #pragma unroll
                for (int it = 0; it < 2; it++)
                    bv[it] = *reinterpret_cast<const uint4*>(&g_w1h[(size_t)(ec * 128 + bn[it]) * DD + d0 + bj[it] * 8]);
            }
            uint32_t abase = a_frag_base + buf * (ABUF * 2);
            uint32_t bbase = b_frag_base + buf * (ABUF * 2);
            #pragma unroll
            for (int kk = 0; kk < 2; kk++) {
                uint32_t a[2][4];
                #pragma unroll
                for (int mi = 0; mi < 2; mi++)
                    ldsm_x4(a[mi], abase + mi * (16 * ASTRH * 2) + kk * 32);
                uint32_t b[4][4];
                #pragma unroll
                for (int nb = 0; nb < 4; nb++)
                    ldsm_x4(b[nb], bbase + nb * (16 * ASTRH * 2) + kk * 32);
                #pragma unroll
                for (int mi = 0; mi < 2; mi++)
                    #pragma unroll
                    for (int nb = 0; nb < 4; nb++) {
                        mma_fp16(acc[mi][nb * 2 + 0], a[mi], &b[nb][0]);
                        mma_fp16(acc[mi][nb * 2 + 1], a[mi], &b[nb][2]);
                    }
            }
            if (c < 23) {
                __half* Ad = As + (buf ^ 1) * ABUF;
                __half* Bd = Bs + (buf ^ 1) * ABUF;
                #pragma unroll
                for (int it = 0; it < 4; it++) {
                    float sc = sinv[arow[it]];
                    uint2 u;
                    u.x = pack2(av[it].x * sc, av[it].y * sc);
                    u.y = pack2(av[it].z * sc, av[it].w * sc);
                    *reinterpret_cast<uint2*>(&Ad[arow[it] * ASTRH + ak4[it] * 4]) = u;
                }
                #pragma unroll
                for (int it = 0; it < 2; it++)
                    *reinterpret_cast<uint4*>(&Bd[bn[it] * ASTRH + bj[it] * 8]) = bv[it];
            }
            __syncthreads();
        }

        #pragma unroll
        for (int ni = 0; ni < 8; ni++) {
            int e0 = ec * 128 + wn * 64 + ni * 8 + lr * 2;
            float b1a = __ldg(b1 + e0),     b1b = __ldg(b1 + e0 + 1);
            float w2a = __ldg(w2 + e0),     w2b = __ldg(w2 + e0 + 1);
            #pragma unroll
            for (int mi = 0; mi < 2; mi++) {
                float h;
                h = acc[mi][ni][0] + b1a; if (h > 0.f) yacc[mi * 2 + 0] += h * w2a;
                h = acc[mi][ni][1] + b1b; if (h > 0.f) yacc[mi * 2 + 0] += h * w2b;
                h = acc[mi][ni][2] + b1a; if (h > 0.f) yacc[mi * 2 + 1] += h * w2a;
                h = acc[mi][ni][3] + b1b; if (h > 0.f) yacc[mi * 2 + 1] += h * w2b;
            }
        }
    }

    #pragma unroll
    for (int j = 0; j < 4; j++) {
        yacc[j] += __shfl_xor_sync(0xffffffffu, yacc[j], 1);
        yacc[j] += __shfl_xor_sync(0xffffffffu, yacc[j], 2);
    }
    if (lr == 0) {
        #pragma unroll
        for (int j = 0; j < 4; j++) {
            int row = wm * 32 + (j >> 1) * 16 + (j & 1) * 8 + lq;
            sred[row * 2 + wn] = yacc[j];
        }
    }
    __syncthreads();
    if (t < 128)
        g_y[rt * LL + t] = sred[t * 2] + sred[t * 2 + 1] + __ldg(b2);
}

// ---------------------------------------------------------------------------
// Kernel 3: out = y_ctx + y_ent[argmax]
// ---------------------------------------------------------------------------
__global__ void finalize_kernel(float* __restrict__ out) {
    int i  = blockIdx.x * 256 + threadIdx.x;
    int bk = i >> 7;
    float yc = g_y[(bk * 2) * LL + (i & 127)];
    float ye = g_y[(bk * 2 + 1) * LL + g_arg[i]];
    out[i] = yc + ye;
}

extern "C" void kernel_launch(void* const* d_in, const int* in_sizes, int n_in,
                              void* d_out, int out_size) {
    const float* context = (const float*)d_in[0];
    const float* w1      = (const float*)d_in[1];
    const float* b1      = (const float*)d_in[2];
    const float* w2      = (const float*)d_in[3];
    const float* b2      = (const float*)d_in[4];
    float* out = (float*)d_out;

    cudaFuncSetAttribute(scores_tc_kernel,
                         cudaFuncAttributeMaxDynamicSharedMemorySize, SC_SMEM);
    cudaFuncSetAttribute(mlp_tc_kernel,
                         cudaFuncAttributeMaxDynamicSharedMemorySize, MLP_SMEM);

    prep_w1_kernel<<<DD, 256>>>(w1);
    scores_tc_kernel<<<NBK, 256, SC_SMEM>>>(context);
    mlp_tc_kernel<<<NROWS / 128, 256, MLP_SMEM>>>(context, b1, w2, b2);
    finalize_kernel<<<NOUT / 256, 256>>>(out);
}

// round 8
// speedup vs baseline: 1.4805x; 1.0321x over previous
#include <cuda_runtime.h>
#include <cuda_fp16.h>
#include <math.h>
#include <stdint.h>

// Problem constants: B=4, K=64, L=128, D=768
#define NBK   256
#define LL    128
#define DD    768
#define NROWS 65536
#define NOUT  32768
#define EPSV  1e-8f

#define ASTRH 40    // fp16 smem row stride (80 B), ldmatrix conflict-free

// Scratch
__device__ float  g_norm[NROWS];
__device__ int    g_arg[NOUT];
__device__ float  g_y[NROWS];
__device__ __half g_w1h[DD * DD];   // w1^T fp16 [e][d]

__device__ __forceinline__ void ldsm_x4(uint32_t* r, uint32_t addr) {
    asm volatile("ldmatrix.sync.aligned.m8n8.x4.shared.b16 {%0,%1,%2,%3}, [%4];"
        : "=r"(r[0]), "=r"(r[1]), "=r"(r[2]), "=r"(r[3]) : "r"(addr));
}
__device__ __forceinline__ void mma_fp16(float* d, const uint32_t* a, const uint32_t* b) {
    asm volatile(
        "mma.sync.aligned.m16n8k16.row.col.f32.f16.f16.f32 "
        "{%0,%1,%2,%3}, {%4,%5,%6,%7}, {%8,%9}, {%0,%1,%2,%3};"
        : "+f"(d[0]), "+f"(d[1]), "+f"(d[2]), "+f"(d[3])
        : "r"(a[0]), "r"(a[1]), "r"(a[2]), "r"(a[3]), "r"(b[0]), "r"(b[1]));
}
__device__ __forceinline__ uint32_t smem_u32(const void* p) {
    uint32_t a;
    asm("{ .reg .u64 t; cvta.to.shared.u64 t, %1; cvt.u32.u64 %0, t; }" : "=r"(a) : "l"(p));
    return a;
}
__device__ __forceinline__ uint32_t pack2(float x, float y) {
    __half2 h = __floats2half2_rn(x, y);
    return *reinterpret_cast<uint32_t*>(&h);
}
// split float pair into fp16 hi + fp16 lo-residual
__device__ __forceinline__ void split2(float x, float y, uint32_t& hi, uint32_t& lo) {
    __half hx = __float2half_rn(x), hy = __float2half_rn(y);
    float lx = x - __half2float(hx);
    float ly = y - __half2float(hy);
    __half2 hh = __halves2half2(hx, hy);
    hi = *reinterpret_cast<uint32_t*>(&hh);
    lo = pack2(lx, ly);
}

// ---------------------------------------------------------------------------
// Kernel 0: w1 -> fp16, transposed to [e][d]
// ---------------------------------------------------------------------------
__global__ void prep_w1_kernel(const float* __restrict__ w1) {
    int e = blockIdx.x;
    for (int d = threadIdx.x; d < DD; d += 256)
        g_w1h[e * DD + d] = __float2half_rn(__ldg(w1 + (size_t)d * DD + e));
}

// ---------------------------------------------------------------------------
// Kernel 1: scores via split-fp16 tensor cores (3-term, fp32-exact class)
// + fused row norms + in-register exact argmax (first-index tie-break).
// ---------------------------------------------------------------------------
#define SC_AH   0                  // 10240 B each tile, single-buffered
#define SC_AL   10240
#define SC_BH   20480
#define SC_BL   30720
#define SC_SNA  40960              // f32[128]
#define SC_SNB  41472              // f32[128]
#define SC_RV   41984              // f32[256]
#define SC_RI   43008              // i32[256]
#define SC_SMEM 44032

__global__ __launch_bounds__(256, 2) void scores_split_kernel(const float* __restrict__ x) {
    extern __shared__ char smem[];
    uint32_t sb = smem_u32(smem);
    __half* Ah = reinterpret_cast<__half*>(smem + SC_AH);
    __half* Al = reinterpret_cast<__half*>(smem + SC_AL);
    __half* Bh = reinterpret_cast<__half*>(smem + SC_BH);
    __half* Bl = reinterpret_cast<__half*>(smem + SC_BL);
    float*  snA = reinterpret_cast<float*>(smem + SC_SNA);
    float*  snB = reinterpret_cast<float*>(smem + SC_SNB);
    float*  rv  = reinterpret_cast<float*>(smem + SC_RV);
    int*    ri  = reinterpret_cast<int*>(smem + SC_RI);

    int bk = blockIdx.x;
    const float* ctx = x + (size_t)(bk * 2) * LL * DD;
    const float* ent = ctx + (size_t)LL * DD;

    int t    = threadIdx.x;
    int lane = t & 31;
    int wid  = t >> 5;
    int wm   = wid & 3;
    int wn   = wid >> 2;
    int lq   = lane >> 2;
    int lr   = lane & 3;

    int arow[4], ak4[4];
    #pragma unroll
    for (int it = 0; it < 4; it++) {
        int idx = t + it * 256;
        arow[it] = idx >> 3;  ak4[it] = idx & 7;
    }

    uint32_t frag_a = (uint32_t)(((wm * 32 + (lane & 15)) * ASTRH + (lane >> 4) * 8) * 2);
    uint32_t b_row_off = ((lane >> 4) * 8 + (lane & 7));
    uint32_t b_k_off   = ((lane >> 3) & 1) * 8;
    uint32_t frag_b = (uint32_t)(((wn * 64 + b_row_off) * ASTRH + b_k_off) * 2);

    uint32_t ah_base = sb + SC_AH + frag_a;
    uint32_t al_base = sb + SC_AL + frag_a;
    uint32_t bh_base = sb + SC_BH + frag_b;
    uint32_t bl_base = sb + SC_BL + frag_b;

    float acc[2][8][4];
    #pragma unroll
    for (int mi = 0; mi < 2; mi++)
        #pragma unroll
        for (int ni = 0; ni < 8; ni++)
            #pragma unroll
            for (int c = 0; c < 4; c++) acc[mi][ni][c] = 0.f;

    float nsA[4] = {0.f, 0.f, 0.f, 0.f};
    float nsB[4] = {0.f, 0.f, 0.f, 0.f};

    float4 av[4], bw[4];
    #pragma unroll
    for (int it = 0; it < 4; it++) {
        av[it] = *reinterpret_cast<const float4*>(ctx + (size_t)arow[it] * DD + ak4[it] * 4);
        bw[it] = *reinterpret_cast<const float4*>(ent + (size_t)arow[it] * DD + ak4[it] * 4);
        nsA[it] += av[it].x * av[it].x + av[it].y * av[it].y + av[it].z * av[it].z + av[it].w * av[it].w;
        nsB[it] += bw[it].x * bw[it].x + bw[it].y * bw[it].y + bw[it].z * bw[it].z + bw[it].w * bw[it].w;
    }

    for (int c = 0; c < 24; c++) {
        // store current chunk (split hi/lo) to smem tiles
        #pragma unroll
        for (int it = 0; it < 4; it++) {
            uint32_t off = arow[it] * ASTRH + ak4[it] * 4;
            uint2 h, l;
            split2(av[it].x, av[it].y, h.x, l.x);
            split2(av[it].z, av[it].w, h.y, l.y);
            *reinterpret_cast<uint2*>(&Ah[off]) = h;
            *reinterpret_cast<uint2*>(&Al[off]) = l;
            split2(bw[it].x, bw[it].y, h.x, l.x);
            split2(bw[it].z, bw[it].w, h.y, l.y);
            *reinterpret_cast<uint2*>(&Bh[off]) = h;
            *reinterpret_cast<uint2*>(&Bl[off]) = l;
        }
        __syncthreads();
        // prefetch next chunk + norms
        if (c < 23) {
            int d0 = (c + 1) * 32;
            #pragma unroll
            for (int it = 0; it < 4; it++) {
                av[it] = *reinterpret_cast<const float4*>(ctx + (size_t)arow[it] * DD + d0 + ak4[it] * 4);
                bw[it] = *reinterpret_cast<const float4*>(ent + (size_t)arow[it] * DD + d0 + ak4[it] * 4);
                nsA[it] += av[it].x * av[it].x + av[it].y * av[it].y + av[it].z * av[it].z + av[it].w * av[it].w;
                nsB[it] += bw[it].x * bw[it].x + bw[it].y * bw[it].y + bw[it].z * bw[it].z + bw[it].w * bw[it].w;
            }
        }
        // compute: 3 split terms (hh, lh, hl)
        #pragma unroll
        for (int kk = 0; kk < 2; kk++) {
            uint32_t ah[2][4], al[2][4];
            #pragma unroll
            for (int mi = 0; mi < 2; mi++) {
                ldsm_x4(ah[mi], ah_base + mi * (16 * ASTRH * 2) + kk * 32);
                ldsm_x4(al[mi], al_base + mi * (16 * ASTRH * 2) + kk * 32);
            }
            #pragma unroll
            for (int nb = 0; nb < 4; nb++) {
                uint32_t bh[4];
                ldsm_x4(bh, bh_base + nb * (16 * ASTRH * 2) + kk * 32);
                #pragma unroll
                for (int mi = 0; mi < 2; mi++) {
                    mma_fp16(acc[mi][nb * 2 + 0], ah[mi], &bh[0]);
                    mma_fp16(acc[mi][nb * 2 + 1], ah[mi], &bh[2]);
                    mma_fp16(acc[mi][nb * 2 + 0], al[mi], &bh[0]);
                    mma_fp16(acc[mi][nb * 2 + 1], al[mi], &bh[2]);
                }
                uint32_t bl[4];
                ldsm_x4(bl, bl_base + nb * (16 * ASTRH * 2) + kk * 32);
                #pragma unroll
                for (int mi = 0; mi < 2; mi++) {
                    mma_fp16(acc[mi][nb * 2 + 0], ah[mi], &bl[0]);
                    mma_fp16(acc[mi][nb * 2 + 1], ah[mi], &bl[2]);
                }
            }
        }
        __syncthreads();
    }

    // finish norms: reduce over the 8 lanes sharing a row
    #pragma unroll
    for (int it = 0; it < 4; it++) {
        float sA = nsA[it], sB = nsB[it];
        #pragma unroll
        for (int o = 1; o < 8; o <<= 1) {
            sA += __shfl_xor_sync(0xffffffffu, sA, o);
            sB += __shfl_xor_sync(0xffffffffu, sB, o);
        }
        if ((t & 7) == 0) {
            int row = arow[it];
            float na = sqrtf(sA), nb = sqrtf(sB);
            snA[row] = na;
            snB[row] = nb;
            g_norm[(bk * 2) * LL + row]     = na;
            g_norm[(bk * 2 + 1) * LL + row] = nb;
        }
    }
    __syncthreads();

    // in-register argmax; slots s = mi*2 + half: row = wm*32 + mi*16 + half*8 + lq
    float bv[4];
    int   bi4[4];
    float nl[4];
    #pragma unroll
    for (int s = 0; s < 4; s++) {
        bv[s] = -3.4e38f; bi4[s] = 0;
        nl[s] = snA[wm * 32 + (s >> 1) * 16 + (s & 1) * 8 + lq];
    }
    #pragma unroll
    for (int ni = 0; ni < 8; ni++) {
        int col0 = wn * 64 + ni * 8 + lr * 2;
        float nm0 = snB[col0], nm1 = snB[col0 + 1];
        #pragma unroll
        for (int mi = 0; mi < 2; mi++) {
            float c0 = acc[mi][ni][0] / (nl[mi * 2] * nm0 + EPSV);
            if (c0 > bv[mi * 2]) { bv[mi * 2] = c0; bi4[mi * 2] = col0; }
            float c1 = acc[mi][ni][1] / (nl[mi * 2] * nm1 + EPSV);
            if (c1 > bv[mi * 2]) { bv[mi * 2] = c1; bi4[mi * 2] = col0 + 1; }
            float c2 = acc[mi][ni][2] / (nl[mi * 2 + 1] * nm0 + EPSV);
            if (c2 > bv[mi * 2 + 1]) { bv[mi * 2 + 1] = c2; bi4[mi * 2 + 1] = col0; }
            float c3 = acc[mi][ni][3] / (nl[mi * 2 + 1] * nm1 + EPSV);
            if (c3 > bv[mi * 2 + 1]) { bv[mi * 2 + 1] = c3; bi4[mi * 2 + 1] = col0 + 1; }
        }
    }
    // reduce across the 4 lanes sharing a row (lr bits), tie -> lower col
    #pragma unroll
    for (int s = 0; s < 4; s++) {
        #pragma unroll
        for (int o = 1; o <= 2; o <<= 1) {
            float ov = __shfl_xor_sync(0xffffffffu, bv[s], o);
            int   oi = __shfl_xor_sync(0xffffffffu, bi4[s], o);
            if (ov > bv[s] || (ov == bv[s] && oi < bi4[s])) { bv[s] = ov; bi4[s] = oi; }
        }
    }
    if (lr == 0) {
        #pragma unroll
        for (int s = 0; s < 4; s++) {
            int row = wm * 32 + (s >> 1) * 16 + (s & 1) * 8 + lq;
            rv[row * 2 + wn] = bv[s];
            ri[row * 2 + wn] = bi4[s];
        }
    }
    __syncthreads();
    if (t < 128) {
        float v0 = rv[t * 2], v1 = rv[t * 2 + 1];
        int   i0 = ri[t * 2], i1 = ri[t * 2 + 1];
        int best = (v1 > v0 || (v1 == v0 && i1 < i0)) ? i1 : i0;
        g_arg[bk * LL + t] = best;
    }
}

// ---------------------------------------------------------------------------
// Kernel 2: MLP via fp16 m16n8k16 mma.sync + ldmatrix (R5/R7, validated)
// ---------------------------------------------------------------------------
#define ABUF (128 * ASTRH)
#define MLP_OFF_AS   0
#define MLP_OFF_BS   20480
#define MLP_OFF_SINV 40960
#define MLP_OFF_SRED 41472
#define MLP_SMEM     42496

__global__ __launch_bounds__(256, 2) void mlp_tc_kernel(const float* __restrict__ x,
                                                        const float* __restrict__ b1,
                                                        const float* __restrict__ w2,
                                                        const float* __restrict__ b2) {
    extern __shared__ char smem[];
    __half* As   = reinterpret_cast<__half*>(smem + MLP_OFF_AS);
    __half* Bs   = reinterpret_cast<__half*>(smem + MLP_OFF_BS);
    float*  sinv = reinterpret_cast<float*>(smem + MLP_OFF_SINV);
    float*  sred = reinterpret_cast<float*>(smem + MLP_OFF_SRED);
    uint32_t as_u32 = smem_u32(As);
    uint32_t bs_u32 = smem_u32(Bs);

    int rt = blockIdx.x;
    const float* X = x + (size_t)rt * LL * DD;

    int t    = threadIdx.x;
    int lane = t & 31;
    int wid  = t >> 5;
    int wm   = wid & 3;
    int wn   = wid >> 2;
    int lq   = lane >> 2;
    int lr   = lane & 3;

    if (t < 128) sinv[t] = 1.0f / g_norm[rt * LL + t];
    __syncthreads();

    int arow[4], ak4[4];
    #pragma unroll
    for (int it = 0; it < 4; it++) {
        int idx = t + it * 256;
        arow[it] = idx >> 3;  ak4[it] = idx & 7;
    }
    int bn[2], bj[2];
    #pragma unroll
    for (int it = 0; it < 2; it++) {
        int idx = t + it * 256;
        bn[it] = idx >> 2;  bj[it] = idx & 3;
    }

    uint32_t a_frag_base = as_u32 +
        (uint32_t)(((wm * 32 + (lane & 15)) * ASTRH + (lane >> 4) * 8) * 2);
    uint32_t b_row_off = ((lane >> 4) * 8 + (lane & 7));
    uint32_t b_k_off   = ((lane >> 3) & 1) * 8;
    uint32_t b_frag_base = bs_u32 +
        (uint32_t)(((wn * 64 + b_row_off) * ASTRH + b_k_off) * 2);

    float yacc[4] = {0.f, 0.f, 0.f, 0.f};

    for (int ec = 0; ec < 6; ec++) {
        float acc[2][8][4];
        #pragma unroll
        for (int mi = 0; mi < 2; mi++)
            #pragma unroll
            for (int ni = 0; ni < 8; ni++)
                #pragma unroll
                for (int c = 0; c < 4; c++) acc[mi][ni][c] = 0.f;

        float4 av[4];
        uint4  bv[2];
        #pragma unroll
        for (int it = 0; it < 4; it++)
            av[it] = *reinterpret_cast<const float4*>(X + (size_t)arow[it] * DD + ak4[it] * 4);
        #pragma unroll
        for (int it = 0; it < 2; it++)
            bv[it] = *reinterpret_cast<const uint4*>(&g_w1h[(size_t)(ec * 128 + bn[it]) * DD + bj[it] * 8]);
        #pragma unroll
        for (int it = 0; it < 4; it++) {
            float sc = sinv[arow[it]];
            uint2 u;
            u.x = pack2(av[it].x * sc, av[it].y * sc);
            u.y = pack2(av[it].z * sc, av[it].w * sc);
            *reinterpret_cast<uint2*>(&As[arow[it] * ASTRH + ak4[it] * 4]) = u;
        }
        #pragma unroll
        for (int it = 0; it < 2; it++)
            *reinterpret_cast<uint4*>(&Bs[bn[it] * ASTRH + bj[it] * 8]) = bv[it];
        __syncthreads();

        for (int c = 0; c < 24; c++) {
            int buf = c & 1;
            if (c < 23) {
                int d0 = (c + 1) * 32;
                #pragma unroll
                for (int it = 0; it < 4; it++)
                    av[it] = *reinterpret_cast<const float4*>(X + (size_t)arow[it] * DD + d0 + ak4[it] * 4);
                #pragma unroll
                for (int it = 0; it < 2; it++)
                    bv[it] = *reinterpret_cast<const uint4*>(&g_w1h[(size_t)(ec * 128 + bn[it]) * DD + d0 + bj[it] * 8]);
            }
            uint32_t abase = a_frag_base + buf * (ABUF * 2);
            uint32_t bbase = b_frag_base + buf * (ABUF * 2);
            #pragma unroll
            for (int kk = 0; kk < 2; kk++) {
                uint32_t a[2][4];
                #pragma unroll
                for (int mi = 0; mi < 2; mi++)
                    ldsm_x4(a[mi], abase + mi * (16 * ASTRH * 2) + kk * 32);
                uint32_t b[4][4];
                #pragma unroll
                for (int nb = 0; nb < 4; nb++)
                    ldsm_x4(b[nb], bbase + nb * (16 * ASTRH * 2) + kk * 32);
                #pragma unroll
                for (int mi = 0; mi < 2; mi++)
                    #pragma unroll
                    for (int nb = 0; nb < 4; nb++) {
                        mma_fp16(acc[mi][nb * 2 + 0], a[mi], &b[nb][0]);
                        mma_fp16(acc[mi][nb * 2 + 1], a[mi], &b[nb][2]);
                    }
            }
            if (c < 23) {
                __half* Ad = As + (buf ^ 1) * ABUF;
                __half* Bd = Bs + (buf ^ 1) * ABUF;
                #pragma unroll
                for (int it = 0; it < 4; it++) {
                    float sc = sinv[arow[it]];
                    uint2 u;
                    u.x = pack2(av[it].x * sc, av[it].y * sc);
                    u.y = pack2(av[it].z * sc, av[it].w * sc);
                    *reinterpret_cast<uint2*>(&Ad[arow[it] * ASTRH + ak4[it] * 4]) = u;
                }
                #pragma unroll
                for (int it = 0; it < 2; it++)
                    *reinterpret_cast<uint4*>(&Bd[bn[it] * ASTRH + bj[it] * 8]) = bv[it];
            }
            __syncthreads();
        }

        #pragma unroll
        for (int ni = 0; ni < 8; ni++) {
            int e0 = ec * 128 + wn * 64 + ni * 8 + lr * 2;
            float b1a = __ldg(b1 + e0),     b1b = __ldg(b1 + e0 + 1);
            float w2a = __ldg(w2 + e0),     w2b = __ldg(w2 + e0 + 1);
            #pragma unroll
            for (int mi = 0; mi < 2; mi++) {
                float h;
                h = acc[mi][ni][0] + b1a; if (h > 0.f) yacc[mi * 2 + 0] += h * w2a;
                h = acc[mi][ni][1] + b1b; if (h > 0.f) yacc[mi * 2 + 0] += h * w2b;
                h = acc[mi][ni][2] + b1a; if (h > 0.f) yacc[mi * 2 + 1] += h * w2a;
                h = acc[mi][ni][3] + b1b; if (h > 0.f) yacc[mi * 2 + 1] += h * w2b;
            }
        }
    }

    #pragma unroll
    for (int j = 0; j < 4; j++) {
        yacc[j] += __shfl_xor_sync(0xffffffffu, yacc[j], 1);
        yacc[j] += __shfl_xor_sync(0xffffffffu, yacc[j], 2);
    }
    if (lr == 0) {
        #pragma unroll
        for (int j = 0; j < 4; j++) {
            int row = wm * 32 + (j >> 1) * 16 + (j & 1) * 8 + lq;
            sred[row * 2 + wn] = yacc[j];
        }
    }
    __syncthreads();
    if (t < 128)
        g_y[rt * LL + t] = sred[t * 2] + sred[t * 2 + 1] + __ldg(b2);
}

// ---------------------------------------------------------------------------
// Kernel 3: out = y_ctx + y_ent[argmax]
// ---------------------------------------------------------------------------
__global__ void finalize_kernel(float* __restrict__ out) {
    int i  = blockIdx.x * 256 + threadIdx.x;
    int bk = i >> 7;
    float yc = g_y[(bk * 2) * LL + (i & 127)];
    float ye = g_y[(bk * 2 + 1) * LL + g_arg[i]];
    out[i] = yc + ye;
}

extern "C" void kernel_launch(void* const* d_in, const int* in_sizes, int n_in,
                              void* d_out, int out_size) {
    const float* context = (const float*)d_in[0];
    const float* w1      = (const float*)d_in[1];
    const float* b1      = (const float*)d_in[2];
    const float* w2      = (const float*)d_in[3];
    const float* b2      = (const float*)d_in[4];
    float* out = (float*)d_out;

    cudaFuncSetAttribute(scores_split_kernel,
                         cudaFuncAttributeMaxDynamicSharedMemorySize, SC_SMEM);
    cudaFuncSetAttribute(mlp_tc_kernel,
                         cudaFuncAttributeMaxDynamicSharedMemorySize, MLP_SMEM);

    prep_w1_kernel<<<DD, 256>>>(w1);
    scores_split_kernel<<<NBK, 256, SC_SMEM>>>(context);
    mlp_tc_kernel<<<NROWS / 128, 256, MLP_SMEM>>>(context, b1, w2, b2);
    finalize_kernel<<<NOUT / 256, 256>>>(out);
}